// round 1
// baseline (speedup 1.0000x reference)
#include <cuda_runtime.h>
#include <cuda_bf16.h>
#include <math.h>

#define N_NODES 50000
#define NODE_DIM 64
#define DEPTH 2
#define FEAT 192           // 64*(DEPTH+1)
#define E_EDGES 1200000
#define R_REL 500
#define DEG 24

// ---------------- scratch (device globals: allocation-free) ----------------
__device__ float g_nrel[R_REL * NODE_DIM];   // l2-normalized rel_emb
__device__ float g_attW[DEPTH * R_REL];      // per-relation attention logit per layer
__device__ float g_nproxy[64 * FEAT];        // l2-normalized proxy rows

// ---------------- prep: normalize rel table + proxy, build att tables ------
__global__ void prep_kernel(const float* __restrict__ rel_emb,
                            const float* __restrict__ attn_kernels,
                            const float* __restrict__ proxy) {
    int w = (blockIdx.x * blockDim.x + threadIdx.x) >> 5;
    int lane = threadIdx.x & 31;
    if (w < R_REL) {
        float2 v = ((const float2*)(rel_emb + w * NODE_DIM))[lane];
        float ss = v.x * v.x + v.y * v.y;
        #pragma unroll
        for (int o = 16; o; o >>= 1) ss += __shfl_xor_sync(0xffffffffu, ss, o);
        float inv = 1.0f / fmaxf(sqrtf(ss), 1e-12f);
        float2 nv = make_float2(v.x * inv, v.y * inv);
        ((float2*)(g_nrel + w * NODE_DIM))[lane] = nv;
        float2 a0 = ((const float2*)attn_kernels)[lane];
        float2 a1 = ((const float2*)(attn_kernels + NODE_DIM))[lane];
        float d0 = nv.x * a0.x + nv.y * a0.y;
        float d1 = nv.x * a1.x + nv.y * a1.y;
        #pragma unroll
        for (int o = 16; o; o >>= 1) {
            d0 += __shfl_xor_sync(0xffffffffu, d0, o);
            d1 += __shfl_xor_sync(0xffffffffu, d1, o);
        }
        if (lane == 0) { g_attW[w] = d0; g_attW[R_REL + w] = d1; }
    } else if (w < R_REL + 64) {
        int j = w - R_REL;
        float v[6];
        float ss = 0.f;
        #pragma unroll
        for (int t = 0; t < 6; t++) {
            v[t] = proxy[j * FEAT + lane + 32 * t];
            ss += v[t] * v[t];
        }
        #pragma unroll
        for (int o = 16; o; o >>= 1) ss += __shfl_xor_sync(0xffffffffu, ss, o);
        float inv = 1.0f / fmaxf(sqrtf(ss), 1e-12f);
        #pragma unroll
        for (int t = 0; t < 6; t++) g_nproxy[j * FEAT + lane + 32 * t] = v[t] * inv;
    }
}

// ---------------- layer 0 input: outputs[:,0:64] = tanh(features) ----------
__global__ void tanh_kernel(const float* __restrict__ features, float* __restrict__ out) {
    int idx = blockIdx.x * blockDim.x + threadIdx.x;
    if (idx >= N_NODES * NODE_DIM) return;
    int i = idx >> 6;        // /64
    int j = idx & 63;
    out[i * FEAT + j] = tanhf(features[idx]);
}

// ---------------- graph attention layer: warp per node ---------------------
__global__ void layer_kernel(float* __restrict__ out,
                             const int* __restrict__ src,     // adj[1]
                             const int* __restrict__ rid,     // r_index[1]
                             const float* __restrict__ rval,
                             int l) {
    int w = (blockIdx.x * blockDim.x + threadIdx.x) >> 5;
    int lane = threadIdx.x & 31;
    if (w >= N_NODES) return;
    int base = w * DEG;

    // per-lane edge metadata (lanes 0..23)
    float att = -INFINITY;
    int ms = 0, mr = 0;
    if (lane < DEG) {
        int e = base + lane;
        ms = __ldg(src + e);
        mr = __ldg(rid + e);
        float sgn = __ldg(rval + e) < 0.f ? -1.f : 1.f;
        att = sgn * g_attW[l * R_REL + mr];
    }
    // segment softmax over the 24 edges of this node
    float m = att;
    #pragma unroll
    for (int o = 16; o; o >>= 1) m = fmaxf(m, __shfl_xor_sync(0xffffffffu, m, o));
    float ex = (lane < DEG) ? expf(att - m) : 0.f;
    float s = ex;
    #pragma unroll
    for (int o = 16; o; o >>= 1) s += __shfl_xor_sync(0xffffffffu, s, o);
    float wgt = ex / s;

    const float* fsrc = out + NODE_DIM * l;   // column block l
    float2 acc = make_float2(0.f, 0.f);
    #pragma unroll 4
    for (int e = 0; e < DEG; e++) {
        int   se = __shfl_sync(0xffffffffu, ms, e);
        int   re = __shfl_sync(0xffffffffu, mr, e);
        float we = __shfl_sync(0xffffffffu, wgt, e);
        float2 f = ((const float2*)(fsrc + (long)se * FEAT))[lane];
        float2 r = ((const float2*)(g_nrel + re * NODE_DIM))[lane];
        float d = f.x * r.x + f.y * r.y;
        #pragma unroll
        for (int o = 16; o; o >>= 1) d += __shfl_xor_sync(0xffffffffu, d, o);
        float t2 = 2.f * d;
        acc.x += we * (f.x - t2 * r.x);
        acc.y += we * (f.y - t2 * r.y);
    }
    float* dst = out + (long)w * FEAT + NODE_DIM * (l + 1);
    ((float2*)dst)[lane] = make_float2(tanhf(acc.x), tanhf(acc.y));
}

// ---------------- fused final stage: logits->softmax->pf->gate->out --------
// 256 threads, 64-node tile. smem: nproxy, proxy, o, pf (stride 196) + logits + inv
#define NT 64
#define SSTR 196
__global__ void final_kernel(float* __restrict__ out,          // in-place outputs -> result
                             const float* __restrict__ proxy,
                             const float* __restrict__ gate_w,
                             const float* __restrict__ gate_b) {
    extern __shared__ float smem[];
    float* s_np = smem;                    // 64 x 196
    float* s_px = s_np + NT * SSTR;        // 64 x 196
    float* s_o  = s_px + NT * SSTR;        // 64 x 196
    float* s_pf = s_o  + NT * SSTR;        // 64 x 196
    float* s_lg = s_pf + NT * SSTR;        // 64 x 64
    float* s_inv = s_lg + NT * 64;         // 64

    int tid = threadIdx.x;
    int n0 = blockIdx.x * NT;
    int rows = N_NODES - n0; if (rows > NT) rows = NT;

    // load normalized proxy + raw proxy into smem (padded stride)
    for (int idx = tid; idx < 64 * FEAT; idx += 256) {
        int r = idx / FEAT, k = idx - r * FEAT;
        s_np[r * SSTR + k] = g_nproxy[idx];
        s_px[r * SSTR + k] = __ldg(proxy + idx);
    }
    // load output tile (zero-fill invalid rows)
    for (int idx = tid; idx < NT * FEAT; idx += 256) {
        int r = idx / FEAT, k = idx - r * FEAT;
        s_o[r * SSTR + k] = (r < rows) ? out[(long)(n0 + r) * FEAT + k] : 0.f;
    }
    __syncthreads();

    // row inverse norms (warp per row)
    {
        int wid = tid >> 5, lane = tid & 31;
        for (int r = wid; r < NT; r += 8) {
            float ss = 0.f;
            #pragma unroll
            for (int t = 0; t < 6; t++) {
                float v = s_o[r * SSTR + lane + 32 * t];
                ss += v * v;
            }
            #pragma unroll
            for (int o = 16; o; o >>= 1) ss += __shfl_xor_sync(0xffffffffu, ss, o);
            if (lane == 0) s_inv[r] = 1.0f / fmaxf(sqrtf(ss), 1e-12f);
        }
    }
    __syncthreads();

    int tx = tid & 15, ty = tid >> 4;      // 16x16 thread grid

    // logits[64 x 64] = (o * inv) @ nproxy^T  (k = 192), 4x4 register tile
    {
        float acc[4][4];
        #pragma unroll
        for (int i = 0; i < 4; i++)
            #pragma unroll
            for (int j = 0; j < 4; j++) acc[i][j] = 0.f;
        for (int k = 0; k < FEAT; k += 4) {
            float4 a[4], b[4];
            #pragma unroll
            for (int i = 0; i < 4; i++) a[i] = *(const float4*)&s_o[(ty * 4 + i) * SSTR + k];
            #pragma unroll
            for (int j = 0; j < 4; j++) b[j] = *(const float4*)&s_np[(tx * 4 + j) * SSTR + k];
            #pragma unroll
            for (int i = 0; i < 4; i++)
                #pragma unroll
                for (int j = 0; j < 4; j++)
                    acc[i][j] += a[i].x * b[j].x + a[i].y * b[j].y
                               + a[i].z * b[j].z + a[i].w * b[j].w;
        }
        #pragma unroll
        for (int i = 0; i < 4; i++) {
            int r = ty * 4 + i;
            float inv = s_inv[r];
            #pragma unroll
            for (int j = 0; j < 4; j++)
                s_lg[r * 64 + tx * 4 + j] = acc[i][j] * inv;
        }
    }
    __syncthreads();

    // softmax over 64 per row (warp per row)
    {
        int wid = tid >> 5, lane = tid & 31;
        for (int r = wid; r < NT; r += 8) {
            float v0 = s_lg[r * 64 + lane];
            float v1 = s_lg[r * 64 + 32 + lane];
            float mx = fmaxf(v0, v1);
            #pragma unroll
            for (int o = 16; o; o >>= 1) mx = fmaxf(mx, __shfl_xor_sync(0xffffffffu, mx, o));
            float e0 = expf(v0 - mx), e1 = expf(v1 - mx);
            float sm = e0 + e1;
            #pragma unroll
            for (int o = 16; o; o >>= 1) sm += __shfl_xor_sync(0xffffffffu, sm, o);
            float invs = 1.0f / sm;
            s_lg[r * 64 + lane] = e0 * invs;
            s_lg[r * 64 + 32 + lane] = e1 * invs;
        }
    }
    __syncthreads();

    // pf = o - p @ proxy   (contract over 64 proxies), thread: 4 rows x 12 ks
    {
        float acc[4][12];
        #pragma unroll
        for (int i = 0; i < 4; i++)
            #pragma unroll
            for (int j = 0; j < 12; j++) acc[i][j] = 0.f;
        int kb = tx * 12;
        for (int j = 0; j < 64; j++) {
            float pv[4];
            #pragma unroll
            for (int i = 0; i < 4; i++) pv[i] = s_lg[(ty * 4 + i) * 64 + j];
            float4 b0 = *(const float4*)&s_px[j * SSTR + kb];
            float4 b1 = *(const float4*)&s_px[j * SSTR + kb + 4];
            float4 b2 = *(const float4*)&s_px[j * SSTR + kb + 8];
            #pragma unroll
            for (int i = 0; i < 4; i++) {
                acc[i][0] += pv[i] * b0.x;  acc[i][1] += pv[i] * b0.y;
                acc[i][2] += pv[i] * b0.z;  acc[i][3] += pv[i] * b0.w;
                acc[i][4] += pv[i] * b1.x;  acc[i][5] += pv[i] * b1.y;
                acc[i][6] += pv[i] * b1.z;  acc[i][7] += pv[i] * b1.w;
                acc[i][8] += pv[i] * b2.x;  acc[i][9] += pv[i] * b2.y;
                acc[i][10] += pv[i] * b2.z; acc[i][11] += pv[i] * b2.w;
            }
        }
        #pragma unroll
        for (int i = 0; i < 4; i++) {
            int r = ty * 4 + i;
            #pragma unroll
            for (int j = 0; j < 12; j++)
                s_pf[r * SSTR + kb + j] = s_o[r * SSTR + kb + j] - acc[i][j];
        }
    }
    __syncthreads();

    // gate = sigmoid(pf @ W^T + b); out = g*o + (1-g)*pf
    // thread: 4 rows x 12 output cols, k = 192. W rows streamed via L1.
    {
        float acc[4][12];
        #pragma unroll
        for (int i = 0; i < 4; i++)
            #pragma unroll
            for (int j = 0; j < 12; j++) acc[i][j] = 0.f;
        int cb = tx * 12;
        for (int k = 0; k < FEAT; k += 4) {
            float4 a[4];
            #pragma unroll
            for (int i = 0; i < 4; i++) a[i] = *(const float4*)&s_pf[(ty * 4 + i) * SSTR + k];
            #pragma unroll
            for (int j = 0; j < 12; j++) {
                float4 wv = __ldg((const float4*)(gate_w + (long)(cb + j) * FEAT + k));
                #pragma unroll
                for (int i = 0; i < 4; i++)
                    acc[i][j] += a[i].x * wv.x + a[i].y * wv.y
                               + a[i].z * wv.z + a[i].w * wv.w;
            }
        }
        #pragma unroll
        for (int i = 0; i < 4; i++) {
            int r = ty * 4 + i;
            if (r >= rows) continue;
            #pragma unroll
            for (int j = 0; j < 12; j++) {
                int c = cb + j;
                float pre = acc[i][j] + __ldg(gate_b + c);
                float g = 1.0f / (1.0f + expf(-pre));
                float ov = s_o[r * SSTR + c];
                float pv = s_pf[r * SSTR + c];
                out[(long)(n0 + r) * FEAT + c] = g * ov + (1.0f - g) * pv;
            }
        }
    }
}

extern "C" void kernel_launch(void* const* d_in, const int* in_sizes, int n_in,
                              void* d_out, int out_size) {
    const float* features     = (const float*)d_in[0];   // [N,64]
    const float* rel_emb      = (const float*)d_in[1];   // [R,64]
    const float* proxy        = (const float*)d_in[2];   // [64,192]
    const float* gate_w       = (const float*)d_in[3];   // [192,192]
    const float* gate_b       = (const float*)d_in[4];   // [192]
    const float* attn_kernels = (const float*)d_in[5];   // [2,64]
    const int*   adj          = (const int*)d_in[6];     // [2,E]
    const int*   r_index      = (const int*)d_in[7];     // [2,E]
    const float* r_val        = (const float*)d_in[8];   // [E]
    float* out = (float*)d_out;                          // [N,192]

    const int* src = adj + E_EDGES;      // adj[1]
    const int* rid = r_index + E_EDGES;  // r_index[1]

    // 1) prep tables (564 warps)
    prep_kernel<<<(564 * 32 + 255) / 256, 256>>>(rel_emb, attn_kernels, proxy);

    // 2) outputs[:,0:64] = tanh(features)
    tanh_kernel<<<(N_NODES * NODE_DIM + 255) / 256, 256>>>(features, out);

    // 3) two graph-attention layers (warp per node)
    int lgrid = (N_NODES * 32 + 255) / 256;
    layer_kernel<<<lgrid, 256>>>(out, src, rid, r_val, 0);
    layer_kernel<<<lgrid, 256>>>(out, src, rid, r_val, 1);

    // 4) fused proxy-attention + gate, in-place on out
    size_t smem = (size_t)(4 * NT * SSTR + NT * 64 + NT) * sizeof(float);
    cudaFuncSetAttribute(final_kernel, cudaFuncAttributeMaxDynamicSharedMemorySize, (int)smem);
    final_kernel<<<(N_NODES + NT - 1) / NT, 256, smem>>>(out, proxy, gate_w, gate_b);
}

// round 2
// speedup vs baseline: 2.7619x; 2.7619x over previous
#include <cuda_runtime.h>
#include <cuda_bf16.h>
#include <math.h>

#define N_NODES 50000
#define NODE_DIM 64
#define DEPTH 2
#define FEAT 192           // 64*(DEPTH+1)
#define E_EDGES 1200000
#define R_REL 500
#define DEG 24

// ---------------- scratch (device globals: allocation-free) ----------------
__device__ float g_nrel[R_REL * NODE_DIM];   // l2-normalized rel_emb
__device__ float g_attW[DEPTH * R_REL];      // per-relation attention logit per layer
__device__ float g_npT[FEAT * 64];           // normalized proxy, TRANSPOSED [k][n]
__device__ float g_Wt[FEAT * FEAT];          // gate_w transposed [k][c]

// ---------------- prep: normalize rel table + proxy(->transposed) ----------
__global__ void prep_kernel(const float* __restrict__ rel_emb,
                            const float* __restrict__ attn_kernels,
                            const float* __restrict__ proxy) {
    int w = (blockIdx.x * blockDim.x + threadIdx.x) >> 5;
    int lane = threadIdx.x & 31;
    if (w < R_REL) {
        float2 v = ((const float2*)(rel_emb + w * NODE_DIM))[lane];
        float ss = v.x * v.x + v.y * v.y;
        #pragma unroll
        for (int o = 16; o; o >>= 1) ss += __shfl_xor_sync(0xffffffffu, ss, o);
        float inv = 1.0f / fmaxf(sqrtf(ss), 1e-12f);
        float2 nv = make_float2(v.x * inv, v.y * inv);
        ((float2*)(g_nrel + w * NODE_DIM))[lane] = nv;
        float2 a0 = ((const float2*)attn_kernels)[lane];
        float2 a1 = ((const float2*)(attn_kernels + NODE_DIM))[lane];
        float d0 = nv.x * a0.x + nv.y * a0.y;
        float d1 = nv.x * a1.x + nv.y * a1.y;
        #pragma unroll
        for (int o = 16; o; o >>= 1) {
            d0 += __shfl_xor_sync(0xffffffffu, d0, o);
            d1 += __shfl_xor_sync(0xffffffffu, d1, o);
        }
        if (lane == 0) { g_attW[w] = d0; g_attW[R_REL + w] = d1; }
    } else if (w < R_REL + 64) {
        int j = w - R_REL;
        float v[6];
        float ss = 0.f;
        #pragma unroll
        for (int t = 0; t < 6; t++) {
            v[t] = proxy[j * FEAT + lane + 32 * t];
            ss += v[t] * v[t];
        }
        #pragma unroll
        for (int o = 16; o; o >>= 1) ss += __shfl_xor_sync(0xffffffffu, ss, o);
        float inv = 1.0f / fmaxf(sqrtf(ss), 1e-12f);
        #pragma unroll
        for (int t = 0; t < 6; t++)
            g_npT[(lane + 32 * t) * 64 + j] = v[t] * inv;   // transposed store
    }
}

// ---------------- transpose gate_w -> g_Wt [k][c] ---------------------------
__global__ void transW_kernel(const float* __restrict__ gw) {
    int idx = blockIdx.x * blockDim.x + threadIdx.x;
    if (idx >= FEAT * FEAT) return;
    int k = idx / FEAT, c = idx - k * FEAT;
    g_Wt[idx] = gw[c * FEAT + k];
}

// ---------------- layer 0 input: outputs[:,0:64] = tanh(features) ----------
__global__ void tanh_kernel(const float* __restrict__ features, float* __restrict__ out) {
    int idx = blockIdx.x * blockDim.x + threadIdx.x;
    if (idx >= N_NODES * NODE_DIM) return;
    int i = idx >> 6;
    int j = idx & 63;
    out[i * FEAT + j] = tanhf(features[idx]);
}

// ---------------- graph attention layer: warp per node ---------------------
__global__ void layer_kernel(float* __restrict__ out,
                             const int* __restrict__ src,
                             const int* __restrict__ rid,
                             const float* __restrict__ rval,
                             int l) {
    int w = (blockIdx.x * blockDim.x + threadIdx.x) >> 5;
    int lane = threadIdx.x & 31;
    if (w >= N_NODES) return;
    int base = w * DEG;

    float att = -INFINITY;
    int ms = 0, mr = 0;
    if (lane < DEG) {
        int e = base + lane;
        ms = __ldg(src + e);
        mr = __ldg(rid + e);
        float sgn = __ldg(rval + e) < 0.f ? -1.f : 1.f;
        att = sgn * g_attW[l * R_REL + mr];
    }
    float m = att;
    #pragma unroll
    for (int o = 16; o; o >>= 1) m = fmaxf(m, __shfl_xor_sync(0xffffffffu, m, o));
    float ex = (lane < DEG) ? expf(att - m) : 0.f;
    float s = ex;
    #pragma unroll
    for (int o = 16; o; o >>= 1) s += __shfl_xor_sync(0xffffffffu, s, o);
    float wgt = ex / s;

    const float* fsrc = out + NODE_DIM * l;
    float2 acc = make_float2(0.f, 0.f);
    #pragma unroll 4
    for (int e = 0; e < DEG; e++) {
        int   se = __shfl_sync(0xffffffffu, ms, e);
        int   re = __shfl_sync(0xffffffffu, mr, e);
        float we = __shfl_sync(0xffffffffu, wgt, e);
        float2 f = ((const float2*)(fsrc + (long)se * FEAT))[lane];
        float2 r = ((const float2*)(g_nrel + re * NODE_DIM))[lane];
        float d = f.x * r.x + f.y * r.y;
        #pragma unroll
        for (int o = 16; o; o >>= 1) d += __shfl_xor_sync(0xffffffffu, d, o);
        float t2 = 2.f * d;
        acc.x += we * (f.x - t2 * r.x);
        acc.y += we * (f.y - t2 * r.y);
    }
    float* dst = out + (long)w * FEAT + NODE_DIM * (l + 1);
    ((float2*)dst)[lane] = make_float2(tanhf(acc.x), tanhf(acc.y));
}

// ---------------- tf32 mma helpers -----------------------------------------
__device__ __forceinline__ void mma8(float* d, const unsigned* a, const unsigned* b) {
    asm volatile(
        "mma.sync.aligned.m16n8k8.row.col.f32.tf32.tf32.f32 "
        "{%0,%1,%2,%3}, {%4,%5,%6,%7}, {%8,%9}, {%0,%1,%2,%3};\n"
        : "+f"(d[0]), "+f"(d[1]), "+f"(d[2]), "+f"(d[3])
        : "r"(a[0]), "r"(a[1]), "r"(a[2]), "r"(a[3]), "r"(b[0]), "r"(b[1]));
}
__device__ __forceinline__ unsigned f2tf(float x) {
    unsigned r;
    asm("cvt.rna.tf32.f32 %0, %1;" : "=r"(r) : "f"(x));
    return r;
}

// ---------------- fused final stage (tensor-core tf32) ----------------------
// block = 256 threads (8 warps), tile = 64 nodes.
// smem: s_x [64 x 196] (o, fp32), s_aux [64 x 196] (pf), s_p [64 x 68], s_inv[64]
#define NT 64
#define SX 196
#define SP 68
__global__ void __launch_bounds__(256) final_kernel(
        float* __restrict__ out,
        const float* __restrict__ proxy,     // [64 x 192] == B[k][n] for GEMM2
        const float* __restrict__ gate_b) {
    extern __shared__ float smem[];
    float* s_x   = smem;                    // 64*196
    float* s_aux = s_x + NT * SX;           // 64*196
    float* s_p   = s_aux + NT * SX;         // 64*68
    float* s_inv = s_p + NT * SP;           // 64

    int tid = threadIdx.x;
    int w = tid >> 5, lane = tid & 31;
    int g = lane >> 2, t = lane & 3;
    int n0 = blockIdx.x * NT;
    int rows = N_NODES - n0; if (rows > NT) rows = NT;

    // ---- load o tile (zero-fill past end) ----
    for (int i = tid; i < NT * 48; i += 256) {
        int r = i / 48, c4 = (i - r * 48) * 4;
        float4 v = (r < rows) ? *(const float4*)(out + (long)(n0 + r) * FEAT + c4)
                              : make_float4(0.f, 0.f, 0.f, 0.f);
        *(float4*)&s_x[r * SX + c4] = v;
    }
    __syncthreads();

    // ---- row inverse norms (warp per 8 rows) ----
    for (int r = w * 8; r < w * 8 + 8; r++) {
        float ss = 0.f;
        #pragma unroll
        for (int tt = 0; tt < 6; tt++) {
            float v = s_x[r * SX + lane + 32 * tt];
            ss += v * v;
        }
        #pragma unroll
        for (int o = 16; o; o >>= 1) ss += __shfl_xor_sync(0xffffffffu, ss, o);
        if (lane == 0) s_inv[r] = 1.0f / fmaxf(sqrtf(ss), 1e-12f);
    }
    __syncthreads();

    // ---- GEMM1: logits[64x64] = o @ nproxy^T, warp w owns n-cols [8w,8w+8) ----
    {
        float d1[4][4];
        #pragma unroll
        for (int mi = 0; mi < 4; mi++)
            #pragma unroll
            for (int q = 0; q < 4; q++) d1[mi][q] = 0.f;
        for (int k0 = 0; k0 < FEAT; k0 += 8) {
            unsigned b[2];
            b[0] = f2tf(__ldg(&g_npT[(k0 + t) * 64 + 8 * w + g]));
            b[1] = f2tf(__ldg(&g_npT[(k0 + t + 4) * 64 + 8 * w + g]));
            #pragma unroll
            for (int mi = 0; mi < 4; mi++) {
                int r0 = 16 * mi + g;
                unsigned a[4];
                a[0] = f2tf(s_x[r0 * SX + k0 + t]);
                a[1] = f2tf(s_x[(r0 + 8) * SX + k0 + t]);
                a[2] = f2tf(s_x[r0 * SX + k0 + t + 4]);
                a[3] = f2tf(s_x[(r0 + 8) * SX + k0 + t + 4]);
                mma8(d1[mi], a, b);
            }
        }
        #pragma unroll
        for (int mi = 0; mi < 4; mi++) {
            int r0 = 16 * mi + g;
            int c = 8 * w + 2 * t;
            float i0 = s_inv[r0], i1 = s_inv[r0 + 8];
            s_p[r0 * SP + c]       = d1[mi][0] * i0;
            s_p[r0 * SP + c + 1]   = d1[mi][1] * i0;
            s_p[(r0 + 8) * SP + c]     = d1[mi][2] * i1;
            s_p[(r0 + 8) * SP + c + 1] = d1[mi][3] * i1;
        }
    }
    __syncthreads();

    // ---- softmax over 64 per row (warp per row) ----
    for (int r = w * 8; r < w * 8 + 8; r++) {
        float v0 = s_p[r * SP + lane];
        float v1 = s_p[r * SP + 32 + lane];
        float mx = fmaxf(v0, v1);
        #pragma unroll
        for (int o = 16; o; o >>= 1) mx = fmaxf(mx, __shfl_xor_sync(0xffffffffu, mx, o));
        float e0 = expf(v0 - mx), e1 = expf(v1 - mx);
        float sm = e0 + e1;
        #pragma unroll
        for (int o = 16; o; o >>= 1) sm += __shfl_xor_sync(0xffffffffu, sm, o);
        float invs = 1.0f / sm;
        s_p[r * SP + lane] = e0 * invs;
        s_p[r * SP + 32 + lane] = e1 * invs;
    }
    __syncthreads();

    // ---- GEMM2: P @ proxy -> pf = o - that (warp w cols [24w, 24w+24)) ----
    {
        float d2[3][4][4];
        #pragma unroll
        for (int ni = 0; ni < 3; ni++)
            #pragma unroll
            for (int mi = 0; mi < 4; mi++)
                #pragma unroll
                for (int q = 0; q < 4; q++) d2[ni][mi][q] = 0.f;
        for (int k0 = 0; k0 < 64; k0 += 8) {
            unsigned a[4][4];
            #pragma unroll
            for (int mi = 0; mi < 4; mi++) {
                int r0 = 16 * mi + g;
                a[mi][0] = f2tf(s_p[r0 * SP + k0 + t]);
                a[mi][1] = f2tf(s_p[(r0 + 8) * SP + k0 + t]);
                a[mi][2] = f2tf(s_p[r0 * SP + k0 + t + 4]);
                a[mi][3] = f2tf(s_p[(r0 + 8) * SP + k0 + t + 4]);
            }
            #pragma unroll
            for (int ni = 0; ni < 3; ni++) {
                int cb = 24 * w + 8 * ni + g;
                unsigned b[2];
                b[0] = f2tf(__ldg(&proxy[(k0 + t) * FEAT + cb]));
                b[1] = f2tf(__ldg(&proxy[(k0 + t + 4) * FEAT + cb]));
                #pragma unroll
                for (int mi = 0; mi < 4; mi++) mma8(d2[ni][mi], a[mi], b);
            }
        }
        // pf = o - P@proxy  (each element owned by exactly one thread)
        #pragma unroll
        for (int ni = 0; ni < 3; ni++) {
            int c = 24 * w + 8 * ni + 2 * t;
            #pragma unroll
            for (int mi = 0; mi < 4; mi++) {
                int r0 = 16 * mi + g;
                s_aux[r0 * SX + c]       = s_x[r0 * SX + c]       - d2[ni][mi][0];
                s_aux[r0 * SX + c + 1]   = s_x[r0 * SX + c + 1]   - d2[ni][mi][1];
                s_aux[(r0 + 8) * SX + c]     = s_x[(r0 + 8) * SX + c]     - d2[ni][mi][2];
                s_aux[(r0 + 8) * SX + c + 1] = s_x[(r0 + 8) * SX + c + 1] - d2[ni][mi][3];
            }
        }
    }
    __syncthreads();

    // ---- GEMM3: pf @ W^T + b -> sigmoid gate -> blend -> global ----
    {
        float d3[3][4][4];
        #pragma unroll
        for (int ni = 0; ni < 3; ni++)
            #pragma unroll
            for (int mi = 0; mi < 4; mi++)
                #pragma unroll
                for (int q = 0; q < 4; q++) d3[ni][mi][q] = 0.f;
        for (int k0 = 0; k0 < FEAT; k0 += 8) {
            unsigned a[4][4];
            #pragma unroll
            for (int mi = 0; mi < 4; mi++) {
                int r0 = 16 * mi + g;
                a[mi][0] = f2tf(s_aux[r0 * SX + k0 + t]);
                a[mi][1] = f2tf(s_aux[(r0 + 8) * SX + k0 + t]);
                a[mi][2] = f2tf(s_aux[r0 * SX + k0 + t + 4]);
                a[mi][3] = f2tf(s_aux[(r0 + 8) * SX + k0 + t + 4]);
            }
            #pragma unroll
            for (int ni = 0; ni < 3; ni++) {
                int cb = 24 * w + 8 * ni + g;
                unsigned b[2];
                b[0] = f2tf(__ldg(&g_Wt[(k0 + t) * FEAT + cb]));
                b[1] = f2tf(__ldg(&g_Wt[(k0 + t + 4) * FEAT + cb]));
                #pragma unroll
                for (int mi = 0; mi < 4; mi++) mma8(d3[ni][mi], a[mi], b);
            }
        }
        // epilogue: gate, blend, store
        #pragma unroll
        for (int ni = 0; ni < 3; ni++) {
            int c = 24 * w + 8 * ni + 2 * t;
            float b0 = __ldg(gate_b + c), b1 = __ldg(gate_b + c + 1);
            #pragma unroll
            for (int mi = 0; mi < 4; mi++) {
                int r0 = 16 * mi + g;
                #pragma unroll
                for (int half = 0; half < 2; half++) {
                    int r = r0 + 8 * half;
                    if (r >= rows) continue;
                    float p0 = d3[ni][mi][2 * half]     + b0;
                    float p1 = d3[ni][mi][2 * half + 1] + b1;
                    float g0 = 1.0f / (1.0f + expf(-p0));
                    float g1 = 1.0f / (1.0f + expf(-p1));
                    float o0 = s_x[r * SX + c],     pf0 = s_aux[r * SX + c];
                    float o1 = s_x[r * SX + c + 1], pf1 = s_aux[r * SX + c + 1];
                    float2 res = make_float2(g0 * o0 + (1.0f - g0) * pf0,
                                             g1 * o1 + (1.0f - g1) * pf1);
                    *(float2*)(out + (long)(n0 + r) * FEAT + c) = res;
                }
            }
        }
    }
}

extern "C" void kernel_launch(void* const* d_in, const int* in_sizes, int n_in,
                              void* d_out, int out_size) {
    const float* features     = (const float*)d_in[0];   // [N,64]
    const float* rel_emb      = (const float*)d_in[1];   // [R,64]
    const float* proxy        = (const float*)d_in[2];   // [64,192]
    const float* gate_w       = (const float*)d_in[3];   // [192,192]
    const float* gate_b       = (const float*)d_in[4];   // [192]
    const float* attn_kernels = (const float*)d_in[5];   // [2,64]
    const int*   adj          = (const int*)d_in[6];     // [2,E]
    const int*   r_index      = (const int*)d_in[7];     // [2,E]
    const float* r_val        = (const float*)d_in[8];   // [E]
    float* out = (float*)d_out;                          // [N,192]

    const int* src = adj + E_EDGES;
    const int* rid = r_index + E_EDGES;

    prep_kernel<<<(564 * 32 + 255) / 256, 256>>>(rel_emb, attn_kernels, proxy);
    transW_kernel<<<(FEAT * FEAT + 255) / 256, 256>>>(gate_w);

    tanh_kernel<<<(N_NODES * NODE_DIM + 255) / 256, 256>>>(features, out);

    int lgrid = (N_NODES * 32 + 255) / 256;
    layer_kernel<<<lgrid, 256>>>(out, src, rid, r_val, 0);
    layer_kernel<<<lgrid, 256>>>(out, src, rid, r_val, 1);

    size_t smem = (size_t)(2 * NT * SX + NT * SP + NT) * sizeof(float);
    cudaFuncSetAttribute(final_kernel, cudaFuncAttributeMaxDynamicSharedMemorySize, (int)smem);
    final_kernel<<<(N_NODES + NT - 1) / NT, 256, smem>>>(out, proxy, gate_b);
}

// round 4
// speedup vs baseline: 3.9197x; 1.4192x over previous
#include <cuda_runtime.h>
#include <cuda_bf16.h>
#include <math.h>

#define N_NODES 50000
#define NODE_DIM 64
#define DEPTH 2
#define FEAT 192           // 64*(DEPTH+1)
#define E_EDGES 1200000
#define R_REL 500
#define DEG 24

// ---------------- scratch (device globals: allocation-free) ----------------
__device__ float    g_nrel[R_REL * NODE_DIM];   // l2-normalized rel_emb
__device__ float    g_attW[DEPTH * R_REL];      // per-relation attention logit per layer
__device__ unsigned g_npT[FEAT * 64];           // normalized proxy, transposed [k][n], tf32 bits
__device__ unsigned g_Wt[FEAT * FEAT];          // gate_w transposed [k][c], tf32 bits
__device__ unsigned g_prx[64 * FEAT];           // proxy [k][n], tf32 bits

__device__ __forceinline__ unsigned f2tf(float x) {
    unsigned r;
    asm("cvt.rna.tf32.f32 %0, %1;" : "=r"(r) : "f"(x));
    return r;
}

// ---------------- prep: normalize rel table + proxy(->transposed tf32) -----
__global__ void prep_kernel(const float* __restrict__ rel_emb,
                            const float* __restrict__ attn_kernels,
                            const float* __restrict__ proxy) {
    int w = (blockIdx.x * blockDim.x + threadIdx.x) >> 5;
    int lane = threadIdx.x & 31;
    if (w < R_REL) {
        float2 v = ((const float2*)(rel_emb + w * NODE_DIM))[lane];
        float ss = v.x * v.x + v.y * v.y;
        #pragma unroll
        for (int o = 16; o; o >>= 1) ss += __shfl_xor_sync(0xffffffffu, ss, o);
        float inv = 1.0f / fmaxf(sqrtf(ss), 1e-12f);
        float2 nv = make_float2(v.x * inv, v.y * inv);
        ((float2*)(g_nrel + w * NODE_DIM))[lane] = nv;
        float2 a0 = ((const float2*)attn_kernels)[lane];
        float2 a1 = ((const float2*)(attn_kernels + NODE_DIM))[lane];
        float d0 = nv.x * a0.x + nv.y * a0.y;
        float d1 = nv.x * a1.x + nv.y * a1.y;
        #pragma unroll
        for (int o = 16; o; o >>= 1) {
            d0 += __shfl_xor_sync(0xffffffffu, d0, o);
            d1 += __shfl_xor_sync(0xffffffffu, d1, o);
        }
        if (lane == 0) { g_attW[w] = d0; g_attW[R_REL + w] = d1; }
    } else if (w < R_REL + 64) {
        int j = w - R_REL;
        float v[6];
        float ss = 0.f;
        #pragma unroll
        for (int t = 0; t < 6; t++) {
            v[t] = proxy[j * FEAT + lane + 32 * t];
            ss += v[t] * v[t];
        }
        #pragma unroll
        for (int o = 16; o; o >>= 1) ss += __shfl_xor_sync(0xffffffffu, ss, o);
        float inv = 1.0f / fmaxf(sqrtf(ss), 1e-12f);
        #pragma unroll
        for (int t = 0; t < 6; t++)
            g_npT[(lane + 32 * t) * 64 + j] = f2tf(v[t] * inv);   // transposed tf32
    }
}

// ---------------- convert gate_w (transposed) + proxy to tf32 tables --------
__global__ void convtab_kernel(const float* __restrict__ gw,
                               const float* __restrict__ proxy) {
    int idx = blockIdx.x * blockDim.x + threadIdx.x;
    if (idx < FEAT * FEAT) {
        int k = idx / FEAT, c = idx - k * FEAT;
        g_Wt[idx] = f2tf(gw[c * FEAT + k]);
    } else if (idx < FEAT * FEAT + 64 * FEAT) {
        int j = idx - FEAT * FEAT;
        g_prx[j] = f2tf(proxy[j]);
    }
}

// ---------------- layer 0 input: outputs[:,0:64] = tanh(features) ----------
__global__ void tanh_kernel(const float* __restrict__ features, float* __restrict__ out) {
    int idx = blockIdx.x * blockDim.x + threadIdx.x;
    if (idx >= N_NODES * NODE_DIM) return;
    int i = idx >> 6;
    int j = idx & 63;
    out[i * FEAT + j] = tanhf(features[idx]);
}

// ---------------- graph attention layer: warp per node ---------------------
// Two edges per iteration: half-warps of 16 lanes, float4 (4 dims) per lane.
__global__ void __launch_bounds__(256) layer_kernel(
        float* __restrict__ out,
        const int* __restrict__ src,
        const int* __restrict__ rid,
        const float* __restrict__ rval,
        int l) {
    __shared__ int4 s_meta[8 * DEG];            // per-warp edge table
    int wb = threadIdx.x >> 5;                  // warp in block
    int w = (blockIdx.x * blockDim.x + threadIdx.x) >> 5;
    int lane = threadIdx.x & 31;
    if (w >= N_NODES) return;
    int base = w * DEG;

    // ---- metadata + segment softmax (lanes 0..23 hold one edge each) ----
    float att = -INFINITY;
    int ms = 0, mr = 0;
    if (lane < DEG) {
        int e = base + lane;
        ms = __ldg(src + e);
        mr = __ldg(rid + e);
        float sgn = __ldg(rval + e) < 0.f ? -1.f : 1.f;
        att = sgn * g_attW[l * R_REL + mr];
    }
    float m = att;
    #pragma unroll
    for (int o = 16; o; o >>= 1) m = fmaxf(m, __shfl_xor_sync(0xffffffffu, m, o));
    float ex = (lane < DEG) ? expf(att - m) : 0.f;
    float s = ex;
    #pragma unroll
    for (int o = 16; o; o >>= 1) s += __shfl_xor_sync(0xffffffffu, s, o);
    float wgt = ex / s;

    if (lane < DEG)
        s_meta[wb * DEG + lane] = make_int4(ms * FEAT + NODE_DIM * l,
                                            mr * NODE_DIM,
                                            __float_as_int(wgt), 0);
    __syncwarp();

    // ---- edge loop: 12 iterations x 2 edges ----
    int half = lane >> 4;          // which edge of the pair
    int q4 = (lane & 15) << 2;     // dim offset (4 dims per lane)
    float4 acc = make_float4(0.f, 0.f, 0.f, 0.f);
    #pragma unroll 4
    for (int i = 0; i < 12; i++) {
        int4 md = s_meta[wb * DEG + 2 * i + half];
        float4 f = *(const float4*)(out + md.x + q4);
        float4 r = *(const float4*)(g_nrel + md.y + q4);
        float d = f.x * r.x + f.y * r.y + f.z * r.z + f.w * r.w;
        #pragma unroll
        for (int o = 8; o; o >>= 1) d += __shfl_xor_sync(0xffffffffu, d, o);
        float we = __int_as_float(md.z);
        float t2 = 2.f * d;
        acc.x += we * (f.x - t2 * r.x);
        acc.y += we * (f.y - t2 * r.y);
        acc.z += we * (f.z - t2 * r.z);
        acc.w += we * (f.w - t2 * r.w);
    }
    // combine the two halves (each covered all dims for its edges)
    acc.x += __shfl_xor_sync(0xffffffffu, acc.x, 16);
    acc.y += __shfl_xor_sync(0xffffffffu, acc.y, 16);
    acc.z += __shfl_xor_sync(0xffffffffu, acc.z, 16);
    acc.w += __shfl_xor_sync(0xffffffffu, acc.w, 16);

    if (half == 0) {
        float* dst = out + (long)w * FEAT + NODE_DIM * (l + 1);
        *(float4*)(dst + q4) = make_float4(tanhf(acc.x), tanhf(acc.y),
                                           tanhf(acc.z), tanhf(acc.w));
    }
}

// ---------------- tf32 mma helper -------------------------------------------
__device__ __forceinline__ void mma8(float* d, const unsigned* a, const unsigned* b) {
    asm volatile(
        "mma.sync.aligned.m16n8k8.row.col.f32.tf32.tf32.f32 "
        "{%0,%1,%2,%3}, {%4,%5,%6,%7}, {%8,%9}, {%0,%1,%2,%3};\n"
        : "+f"(d[0]), "+f"(d[1]), "+f"(d[2]), "+f"(d[3])
        : "r"(a[0]), "r"(a[1]), "r"(a[2]), "r"(a[3]), "r"(b[0]), "r"(b[1]));
}

// ---------------- fused final stage (tensor-core tf32) ----------------------
// block = 256 threads (8 warps), tile = 64 nodes. pf overwrites s_x in place.
#define NT 64
#define SX 196
#define SP 68
__global__ void __launch_bounds__(256, 3) final_kernel(
        float* __restrict__ out,
        const float* __restrict__ gate_b) {
    extern __shared__ float smem[];
    float* s_x   = smem;                    // 64*196  (o, later pf)
    float* s_p   = s_x + NT * SX;           // 64*68
    float* s_inv = s_p + NT * SP;           // 64

    int tid = threadIdx.x;
    int w = tid >> 5, lane = tid & 31;
    int g = lane >> 2, t = lane & 3;
    int n0 = blockIdx.x * NT;
    int rows = N_NODES - n0; if (rows > NT) rows = NT;

    // ---- load o tile (zero-fill past end) ----
    for (int i = tid; i < NT * 48; i += 256) {
        int r = i / 48, c4 = (i - r * 48) * 4;
        float4 v = (r < rows) ? *(const float4*)(out + (long)(n0 + r) * FEAT + c4)
                              : make_float4(0.f, 0.f, 0.f, 0.f);
        *(float4*)&s_x[r * SX + c4] = v;
    }
    __syncthreads();

    // ---- row inverse norms (warp per 8 rows) ----
    for (int r = w * 8; r < w * 8 + 8; r++) {
        float ss = 0.f;
        #pragma unroll
        for (int tt = 0; tt < 6; tt++) {
            float v = s_x[r * SX + lane + 32 * tt];
            ss += v * v;
        }
        #pragma unroll
        for (int o = 16; o; o >>= 1) ss += __shfl_xor_sync(0xffffffffu, ss, o);
        if (lane == 0) s_inv[r] = 1.0f / fmaxf(sqrtf(ss), 1e-12f);
    }
    __syncthreads();

    // ---- GEMM1: logits[64x64] = o @ nproxy^T (warp w owns n-cols [8w,8w+8)) ----
    {
        float d1[4][4];
        #pragma unroll
        for (int mi = 0; mi < 4; mi++)
            #pragma unroll
            for (int q = 0; q < 4; q++) d1[mi][q] = 0.f;
        for (int k0 = 0; k0 < FEAT; k0 += 8) {
            unsigned b[2];
            b[0] = __ldg(&g_npT[(k0 + t) * 64 + 8 * w + g]);
            b[1] = __ldg(&g_npT[(k0 + t + 4) * 64 + 8 * w + g]);
            #pragma unroll
            for (int mi = 0; mi < 4; mi++) {
                int r0 = 16 * mi + g;
                unsigned a[4];
                a[0] = f2tf(s_x[r0 * SX + k0 + t]);
                a[1] = f2tf(s_x[(r0 + 8) * SX + k0 + t]);
                a[2] = f2tf(s_x[r0 * SX + k0 + t + 4]);
                a[3] = f2tf(s_x[(r0 + 8) * SX + k0 + t + 4]);
                mma8(d1[mi], a, b);
            }
        }
        #pragma unroll
        for (int mi = 0; mi < 4; mi++) {
            int r0 = 16 * mi + g;
            int c = 8 * w + 2 * t;
            float i0 = s_inv[r0], i1 = s_inv[r0 + 8];
            s_p[r0 * SP + c]       = d1[mi][0] * i0;
            s_p[r0 * SP + c + 1]   = d1[mi][1] * i0;
            s_p[(r0 + 8) * SP + c]     = d1[mi][2] * i1;
            s_p[(r0 + 8) * SP + c + 1] = d1[mi][3] * i1;
        }
    }
    __syncthreads();

    // ---- softmax over 64 per row (warp per row) ----
    for (int r = w * 8; r < w * 8 + 8; r++) {
        float v0 = s_p[r * SP + lane];
        float v1 = s_p[r * SP + 32 + lane];
        float mx = fmaxf(v0, v1);
        #pragma unroll
        for (int o = 16; o; o >>= 1) mx = fmaxf(mx, __shfl_xor_sync(0xffffffffu, mx, o));
        float e0 = expf(v0 - mx), e1 = expf(v1 - mx);
        float sm = e0 + e1;
        #pragma unroll
        for (int o = 16; o; o >>= 1) sm += __shfl_xor_sync(0xffffffffu, sm, o);
        float invs = 1.0f / sm;
        s_p[r * SP + lane] = e0 * invs;
        s_p[r * SP + 32 + lane] = e1 * invs;
    }
    __syncthreads();

    // ---- GEMM2: pf = o - P @ proxy  (warp w cols [24w,24w+24)), in-place ----
    {
        float d2[3][4][4];
        #pragma unroll
        for (int ni = 0; ni < 3; ni++)
            #pragma unroll
            for (int mi = 0; mi < 4; mi++)
                #pragma unroll
                for (int q = 0; q < 4; q++) d2[ni][mi][q] = 0.f;
        for (int k0 = 0; k0 < 64; k0 += 8) {
            unsigned a[4][4];
            #pragma unroll
            for (int mi = 0; mi < 4; mi++) {
                int r0 = 16 * mi + g;
                a[mi][0] = f2tf(s_p[r0 * SP + k0 + t]);
                a[mi][1] = f2tf(s_p[(r0 + 8) * SP + k0 + t]);
                a[mi][2] = f2tf(s_p[r0 * SP + k0 + t + 4]);
                a[mi][3] = f2tf(s_p[(r0 + 8) * SP + k0 + t + 4]);
            }
            #pragma unroll
            for (int ni = 0; ni < 3; ni++) {
                int cb = 24 * w + 8 * ni + g;
                unsigned b[2];
                b[0] = __ldg(&g_prx[(k0 + t) * FEAT + cb]);
                b[1] = __ldg(&g_prx[(k0 + t + 4) * FEAT + cb]);
                #pragma unroll
                for (int mi = 0; mi < 4; mi++) mma8(d2[ni][mi], a[mi], b);
            }
        }
        // pf = o - P@proxy: each element read+written only by its owning thread
        #pragma unroll
        for (int ni = 0; ni < 3; ni++) {
            int c = 24 * w + 8 * ni + 2 * t;
            #pragma unroll
            for (int mi = 0; mi < 4; mi++) {
                int r0 = 16 * mi + g;
                s_x[r0 * SX + c]       = s_x[r0 * SX + c]       - d2[ni][mi][0];
                s_x[r0 * SX + c + 1]   = s_x[r0 * SX + c + 1]   - d2[ni][mi][1];
                s_x[(r0 + 8) * SX + c]     = s_x[(r0 + 8) * SX + c]     - d2[ni][mi][2];
                s_x[(r0 + 8) * SX + c + 1] = s_x[(r0 + 8) * SX + c + 1] - d2[ni][mi][3];
            }
        }
    }
    __syncthreads();

    // ---- GEMM3: pf @ W^T + b -> sigmoid gate -> blend (o re-read) -> global ----
    {
        float d3[3][4][4];
        #pragma unroll
        for (int ni = 0; ni < 3; ni++)
            #pragma unroll
            for (int mi = 0; mi < 4; mi++)
                #pragma unroll
                for (int q = 0; q < 4; q++) d3[ni][mi][q] = 0.f;
        for (int k0 = 0; k0 < FEAT; k0 += 8) {
            unsigned a[4][4];
            #pragma unroll
            for (int mi = 0; mi < 4; mi++) {
                int r0 = 16 * mi + g;
                a[mi][0] = f2tf(s_x[r0 * SX + k0 + t]);
                a[mi][1] = f2tf(s_x[(r0 + 8) * SX + k0 + t]);
                a[mi][2] = f2tf(s_x[r0 * SX + k0 + t + 4]);
                a[mi][3] = f2tf(s_x[(r0 + 8) * SX + k0 + t + 4]);
            }
            #pragma unroll
            for (int ni = 0; ni < 3; ni++) {
                int cb = 24 * w + 8 * ni + g;
                unsigned b[2];
                b[0] = __ldg(&g_Wt[(k0 + t) * FEAT + cb]);
                b[1] = __ldg(&g_Wt[(k0 + t + 4) * FEAT + cb]);
                #pragma unroll
                for (int mi = 0; mi < 4; mi++) mma8(d3[ni][mi], a[mi], b);
            }
        }
        // epilogue
        #pragma unroll
        for (int ni = 0; ni < 3; ni++) {
            int c = 24 * w + 8 * ni + 2 * t;
            float b0 = __ldg(gate_b + c), b1 = __ldg(gate_b + c + 1);
            #pragma unroll
            for (int mi = 0; mi < 4; mi++) {
                int r0 = 16 * mi + g;
                #pragma unroll
                for (int half = 0; half < 2; half++) {
                    int r = r0 + 8 * half;
                    if (r >= rows) continue;
                    float p0 = d3[ni][mi][2 * half]     + b0;
                    float p1 = d3[ni][mi][2 * half + 1] + b1;
                    float g0 = 1.0f / (1.0f + expf(-p0));
                    float g1 = 1.0f / (1.0f + expf(-p1));
                    float2 o2 = *(const float2*)(out + (long)(n0 + r) * FEAT + c);
                    float pf0 = s_x[r * SX + c];
                    float pf1 = s_x[r * SX + c + 1];
                    float2 res = make_float2(g0 * o2.x + (1.0f - g0) * pf0,
                                             g1 * o2.y + (1.0f - g1) * pf1);
                    *(float2*)(out + (long)(n0 + r) * FEAT + c) = res;
                }
            }
        }
    }
}

extern "C" void kernel_launch(void* const* d_in, const int* in_sizes, int n_in,
                              void* d_out, int out_size) {
    const float* features     = (const float*)d_in[0];   // [N,64]
    const float* rel_emb      = (const float*)d_in[1];   // [R,64]
    const float* proxy        = (const float*)d_in[2];   // [64,192]
    const float* gate_w       = (const float*)d_in[3];   // [192,192]
    const float* gate_b       = (const float*)d_in[4];   // [192]
    const float* attn_kernels = (const float*)d_in[5];   // [2,64]
    const int*   adj          = (const int*)d_in[6];     // [2,E]
    const int*   r_index      = (const int*)d_in[7];     // [2,E]
    const float* r_val        = (const float*)d_in[8];   // [E]
    float* out = (float*)d_out;                          // [N,192]

    const int* src = adj + E_EDGES;
    const int* rid = r_index + E_EDGES;

    prep_kernel<<<(564 * 32 + 255) / 256, 256>>>(rel_emb, attn_kernels, proxy);
    convtab_kernel<<<(FEAT * FEAT + 64 * FEAT + 255) / 256, 256>>>(gate_w, proxy);

    tanh_kernel<<<(N_NODES * NODE_DIM + 255) / 256, 256>>>(features, out);

    int lgrid = (N_NODES * 32 + 255) / 256;
    layer_kernel<<<lgrid, 256>>>(out, src, rid, r_val, 0);
    layer_kernel<<<lgrid, 256>>>(out, src, rid, r_val, 1);

    size_t smem = (size_t)(NT * SX + NT * SP + NT) * sizeof(float);
    cudaFuncSetAttribute(final_kernel, cudaFuncAttributeMaxDynamicSharedMemorySize, (int)smem);
    final_kernel<<<(N_NODES + NT - 1) / NT, 256, smem>>>(out, gate_b);
}